// round 11
// baseline (speedup 1.0000x reference)
#include <cuda_runtime.h>
#include <cuda_bf16.h>
#include <cstdint>

#define N_ITEMS 500000
#define DIM 64
#define BATCH 1024
#define QB 256              // queries per CTA (16 warps x 16 rows)
#define THREADS 512
#define ITEM_TILE 64
#define CHUNK 2048          // items per CTA chunk -> 32 tiles
#define NCHUNKS ((N_ITEMS + CHUNK - 1) / CHUNK)   // 245
#define MARGIN 1.5f         // >> 2*eps(bf16 dot) ~ 0.4 worst-case here
#define NINF __uint_as_float(0xFF800000u)
#define FULL 0xFFFFFFFFu

// Cross-CTA reduction scratch: packed (ordered_float(score) << 32) | ~index
__device__ unsigned long long g_best[BATCH];

__device__ __forceinline__ unsigned int f2ord(float f) {
    unsigned int b = __float_as_uint(f);
    return (b & 0x80000000u) ? ~b : (b | 0x80000000u);
}
__device__ __forceinline__ float ord2f(unsigned int o) {
    unsigned int b = (o & 0x80000000u) ? (o & 0x7FFFFFFFu) : ~o;
    return __uint_as_float(b);
}
__device__ __forceinline__ unsigned pack_bf16x2(float x, float y) {
    __nv_bfloat162 p = __floats2bfloat162_rn(x, y);
    return *(unsigned*)&p;
}

__global__ void reset_kernel() {
    int i = blockIdx.x * blockDim.x + threadIdx.x;
    if (i < BATCH)
        g_best[i] = ((unsigned long long)f2ord(NINF) << 32) | 0xFFFFFFFFull;
}

// Exact fp32 rescore; accumulation order IDENTICAL to the R6 exact kernel and
// identical across all CTAs -> deterministic cross-chunk argmax via atomicMax.
__device__ __forceinline__ void rescore(const float* __restrict__ emb,
                                        int qrow, int j, float& be, int& bi) {
    const float4* qa = (const float4*)(emb + (size_t)qrow * DIM);
    const float4* ja = (const float4*)(emb + (size_t)j * DIM);
    float a0 = 0.f, a1 = 0.f;
    #pragma unroll
    for (int p = 0; p < 16; p += 2) {
        float4 x0 = __ldg(qa + p),     y0 = __ldg(ja + p);
        float4 x1 = __ldg(qa + p + 1), y1 = __ldg(ja + p + 1);
        a0 = fmaf(x0.x, y0.x, a0); a0 = fmaf(x0.y, y0.y, a0);
        a0 = fmaf(x0.z, y0.z, a0); a0 = fmaf(x0.w, y0.w, a0);
        a1 = fmaf(x1.x, y1.x, a1); a1 = fmaf(x1.y, y1.y, a1);
        a1 = fmaf(x1.z, y1.z, a1); a1 = fmaf(x1.w, y1.w, a1);
    }
    float acc = a0 + a1;
    if (acc > be || (acc == be && j < bi)) { be = acc; bi = j; }
}

__device__ __forceinline__ void mma16816(float c[4], const unsigned a[4],
                                         unsigned b0, unsigned b1) {
    asm volatile(
        "mma.sync.aligned.m16n8k16.row.col.f32.bf16.bf16.f32 "
        "{%0,%1,%2,%3}, {%4,%5,%6,%7}, {%8,%9}, {%0,%1,%2,%3};"
        : "+f"(c[0]), "+f"(c[1]), "+f"(c[2]), "+f"(c[3])
        : "r"(a[0]), "r"(a[1]), "r"(a[2]), "r"(a[3]), "r"(b0), "r"(b1));
}

// Epilogue for one 16x8 mma result: register-only max + rare rescore.
// Lane t holds rows g=lane>>2 and g+8 ; cols jb+2*(lane&3), +1.
__device__ __forceinline__ void epilogue(
    float c[4], int jb, bool need_mask,
    int self0, int self1, const float* __restrict__ emb,
    float& run0, float& run1,
    float& be0, int& bi0, float& be1, int& bi1, int t)
{
    int col0 = jb + 2 * t, col1 = col0 + 1;
    if (need_mask) {  // self item in tile or partial last tile (rare)
        if (col0 == self0 || col0 >= N_ITEMS) c[0] = NINF;
        if (col1 == self0 || col1 >= N_ITEMS) c[1] = NINF;
        if (col0 == self1 || col0 >= N_ITEMS) c[2] = NINF;
        if (col1 == self1 || col1 >= N_ITEMS) c[3] = NINF;
    }
    float m0 = fmaxf(c[0], c[1]);
    float m1 = fmaxf(c[2], c[3]);
    m0 = fmaxf(m0, __shfl_xor_sync(FULL, m0, 1));
    m0 = fmaxf(m0, __shfl_xor_sync(FULL, m0, 2));
    m1 = fmaxf(m1, __shfl_xor_sync(FULL, m1, 1));
    m1 = fmaxf(m1, __shfl_xor_sync(FULL, m1, 2));
    run0 = fmaxf(run0, m0);
    run1 = fmaxf(run1, m1);
    float thr0 = run0 - MARGIN, thr1 = run1 - MARGIN;
    if (__any_sync(FULL, (m0 >= thr0) || (m1 >= thr1))) {
        if (c[0] >= thr0 && col0 != self0 && col0 < N_ITEMS) rescore(emb, self0, col0, be0, bi0);
        if (c[1] >= thr0 && col1 != self0 && col1 < N_ITEMS) rescore(emb, self0, col1, be0, bi0);
        if (c[2] >= thr1 && col0 != self1 && col0 < N_ITEMS) rescore(emb, self1, col0, be1, bi1);
        if (c[3] >= thr1 && col1 != self1 && col1 < N_ITEMS) rescore(emb, self1, col1, be1, bi1);
    }
}

__global__ __launch_bounds__(THREADS, 2)
void sim_kernel(const float* __restrict__ emb,
                const int* __restrict__ item_idx) {
    __shared__ __align__(16) __nv_bfloat16 qs[QB * DIM];         // 32 KB, linear
    __shared__ __align__(16) __nv_bfloat16 its[ITEM_TILE * DIM]; // 8 KB, swizzled
    __shared__ int selfs[QB];                                    // 1 KB

    const int tid   = threadIdx.x;
    const int warp  = tid >> 5;
    const int lane  = tid & 31;
    const int qbase = blockIdx.y * QB;
    const int wq    = warp * 16;

    // ---- self indices (item_idx is int32 under JAX default promotion)
    for (int q = tid; q < QB; q += THREADS) {
        int s = item_idx[qbase + q] - 1;
        if (s < 0) s += N_ITEMS;               // python negative-index wrap
        selfs[q] = max(0, min(s, N_ITEMS - 1));
    }
    __syncthreads();

    // ---- stage query rows as bf16 (linear, 128B rows)
    for (int i = tid; i < QB * (DIM / 4); i += THREADS) {
        int q = i >> 4, p = i & 15;
        float4 v = __ldg((const float4*)(emb + (size_t)selfs[q] * DIM) + p);
        unsigned lo = pack_bf16x2(v.x, v.y);
        unsigned hi = pack_bf16x2(v.z, v.w);
        *(uint2*)((char*)qs + q * 128 + p * 8) = make_uint2(lo, hi);
    }
    __syncthreads();

    // ---- A fragments: warp's 16 query rows, K=64, resident in 16 regs
    unsigned a[4][4];
    {
        unsigned qaddr = (unsigned)__cvta_generic_to_shared(qs)
                       + (unsigned)((wq + (lane & 15)) * 128 + (lane >> 4) * 16);
        #pragma unroll
        for (int kt = 0; kt < 4; kt++) {
            asm volatile("ldmatrix.sync.aligned.m8n8.x4.shared.b16 {%0,%1,%2,%3}, [%4];"
                         : "=r"(a[kt][0]), "=r"(a[kt][1]), "=r"(a[kt][2]), "=r"(a[kt][3])
                         : "r"(qaddr + kt * 32));
        }
    }

    const int t = lane & 3;             // column pair within mma
    const int g = lane >> 2;            // row within 16-row block
    const int self0 = selfs[wq + g];
    const int self1 = selfs[wq + g + 8];
    const int myrow_self = selfs[wq + (lane & 15)];

    float run0 = NINF, run1 = NINF;     // running approx max (chunk-local)
    float be0 = NINF, be1 = NINF;       // exact best among rescored
    int   bi0 = 0x7FFFFFFF, bi1 = 0x7FFFFFFF;

    const unsigned its_base = (unsigned)__cvta_generic_to_shared(its);
    const int r = lane & 7, h = (lane >> 3) & 1;   // ldmatrix B addressing

    const int cstart = blockIdx.x * CHUNK;
    const int cend   = min(cstart + CHUNK, N_ITEMS);

    for (int tb = cstart; tb < cend; tb += ITEM_TILE) {
        __syncthreads();
        // convert 64x64 fp32 item tile -> swizzled bf16 smem (zero-pad OOB)
        for (int i = tid; i < ITEM_TILE * (DIM / 4); i += THREADS) {
            int it = i >> 4, p = i & 15;
            int j = tb + it;
            float4 v = (j < N_ITEMS)
                     ? __ldg((const float4*)(emb + (size_t)j * DIM) + p)
                     : make_float4(0.f, 0.f, 0.f, 0.f);
            unsigned lo = pack_bf16x2(v.x, v.y);
            unsigned hi = pack_bf16x2(v.z, v.w);
            int byte = it * 128 + ((p * 8) ^ ((it & 7) * 16));
            *(uint2*)((char*)its + byte) = make_uint2(lo, hi);
        }
        __syncthreads();

        bool need_mask =
            (__ballot_sync(FULL, (unsigned)(myrow_self - tb) < (unsigned)ITEM_TILE) != 0u)
            || (tb + ITEM_TILE > N_ITEMS);

        #pragma unroll
        for (int ng = 0; ng < 8; ng += 2) {    // two 8-item groups in flight
            float c0[4] = {0.f, 0.f, 0.f, 0.f};
            float c1[4] = {0.f, 0.f, 0.f, 0.f};
            #pragma unroll
            for (int kt = 0; kt < 4; kt++) {
                unsigned kb = (unsigned)((kt * 32 + h * 16) ^ (r * 16));
                unsigned ad0 = its_base + (unsigned)((ng * 8 + r) * 128) + kb;
                unsigned ad1 = ad0 + 8 * 128;
                unsigned b00, b01, b10, b11;
                asm volatile("ldmatrix.sync.aligned.m8n8.x2.shared.b16 {%0,%1}, [%2];"
                             : "=r"(b00), "=r"(b01) : "r"(ad0));
                asm volatile("ldmatrix.sync.aligned.m8n8.x2.shared.b16 {%0,%1}, [%2];"
                             : "=r"(b10), "=r"(b11) : "r"(ad1));
                mma16816(c0, a[kt], b00, b01);
                mma16816(c1, a[kt], b10, b11);
            }
            epilogue(c0, tb + ng * 8,     need_mask, self0, self1, emb,
                     run0, run1, be0, bi0, be1, bi1, t);
            epilogue(c1, tb + ng * 8 + 8, need_mask, self0, self1, emb,
                     run0, run1, be0, bi0, be1, bi1, t);
        }
    }

    // combine the 4 lanes of each row group (tie -> smaller index)
    #pragma unroll
    for (int m = 1; m <= 2; m <<= 1) {
        float so = __shfl_xor_sync(FULL, be0, m);
        int   io = __shfl_xor_sync(FULL, bi0, m);
        if (so > be0 || (so == be0 && io < bi0)) { be0 = so; bi0 = io; }
        so = __shfl_xor_sync(FULL, be1, m);
        io = __shfl_xor_sync(FULL, bi1, m);
        if (so > be1 || (so == be1 && io < bi1)) { be1 = so; bi1 = io; }
    }
    if (t == 0) {
        if (be0 > NINF) {
            unsigned long long pk =
                ((unsigned long long)f2ord(be0) << 32) | (unsigned)(~bi0);
            atomicMax(&g_best[qbase + wq + g], pk);
        }
        if (be1 > NINF) {
            unsigned long long pk =
                ((unsigned long long)f2ord(be1) << 32) | (unsigned)(~bi1);
            atomicMax(&g_best[qbase + wq + g + 8], pk);
        }
    }
}

__global__ void finalize_kernel(const float* __restrict__ minv,
                                const float* __restrict__ maxv,
                                float* __restrict__ out) {
    int i = blockIdx.x * blockDim.x + threadIdx.x;
    if (i < BATCH) {
        unsigned long long p = g_best[i];
        float raw = ord2f((unsigned int)(p >> 32));
        int   idx = (int)(~(unsigned int)(p & 0xFFFFFFFFull));
        float mn = minv[0], mx = maxv[0];
        float score = (raw - mn) / (mx - mn);
        out[i]         = (float)(idx + 1);   // indices (argmax + 1), exact < 2^24
        out[BATCH + i] = score;              // normalized scores (fp32 output)
    }
}

extern "C" void kernel_launch(void* const* d_in, const int* in_sizes, int n_in,
                              void* d_out, int out_size) {
    const float* emb = (const float*)d_in[0];
    const int*   idx = (const int*)d_in[1];
    const float* mn  = (const float*)d_in[2];
    const float* mx  = (const float*)d_in[3];

    reset_kernel<<<(BATCH + 255) / 256, 256>>>();

    dim3 grid(NCHUNKS, BATCH / QB);
    sim_kernel<<<grid, THREADS>>>(emb, idx);

    finalize_kernel<<<(BATCH + 255) / 256, 256>>>(mn, mx, (float*)d_out);
}

// round 12
// speedup vs baseline: 1.3399x; 1.3399x over previous
#include <cuda_runtime.h>
#include <cuda_bf16.h>
#include <cstdint>

#define N_ITEMS 500000
#define DIM 64
#define BATCH 1024
#define QB 128              // queries per CTA (8 warps x 16 rows)
#define THREADS 256
#define ITEM_TILE 64
#define CHUNK 4096          // items per CTA chunk -> 64 tiles
#define NCHUNKS 123
#define N_PAD (NCHUNKS * CHUNK)        // 503808, zero-padded bf16 copy
#define TILES_PER_CHUNK (CHUNK / ITEM_TILE)  // 64
#define MARGIN 1.5f         // >> 2*eps(bf16 dot) ~ 0.6 worst-case
#define NINF __uint_as_float(0xFF800000u)
#define FULL 0xFFFFFFFFu

// Scratch (static __device__ arrays -- the sanctioned mechanism)
__device__ unsigned long long g_best[BATCH];
__device__ __nv_bfloat16 g_emb16[(size_t)N_PAD * DIM];   // 64.5 MB bf16 copy

__device__ __forceinline__ unsigned int f2ord(float f) {
    unsigned int b = __float_as_uint(f);
    return (b & 0x80000000u) ? ~b : (b | 0x80000000u);
}
__device__ __forceinline__ float ord2f(unsigned int o) {
    unsigned int b = (o & 0x80000000u) ? (o & 0x7FFFFFFFu) : ~o;
    return __uint_as_float(b);
}
__device__ __forceinline__ unsigned pack_bf16x2(float x, float y) {
    __nv_bfloat162 p = __floats2bfloat162_rn(x, y);
    return *(unsigned*)&p;
}

__global__ void reset_kernel() {
    int i = blockIdx.x * blockDim.x + threadIdx.x;
    if (i < BATCH)
        g_best[i] = ((unsigned long long)f2ord(NINF) << 32) | 0xFFFFFFFFull;
}

// fp32 -> bf16 preconversion (zero-pad beyond N_ITEMS)
__global__ void convert_kernel(const float* __restrict__ emb) {
    const int total = N_PAD * (DIM / 4);
    const int real  = N_ITEMS * (DIM / 4);
    for (int i = blockIdx.x * blockDim.x + threadIdx.x; i < total;
         i += gridDim.x * blockDim.x) {
        float4 v = (i < real) ? __ldg((const float4*)emb + i)
                              : make_float4(0.f, 0.f, 0.f, 0.f);
        ((uint2*)g_emb16)[i] = make_uint2(pack_bf16x2(v.x, v.y),
                                          pack_bf16x2(v.z, v.w));
    }
}

// Exact fp32 rescore; accumulation order IDENTICAL to R6 -> deterministic
// cross-chunk argmax via packed atomicMax (tie -> smaller index).
__device__ __forceinline__ void rescore(const float* __restrict__ emb,
                                        int qrow, int j, float& be, int& bi) {
    const float4* qa = (const float4*)(emb + (size_t)qrow * DIM);
    const float4* ja = (const float4*)(emb + (size_t)j * DIM);
    float a0 = 0.f, a1 = 0.f;
    #pragma unroll
    for (int p = 0; p < 16; p += 2) {
        float4 x0 = __ldg(qa + p),     y0 = __ldg(ja + p);
        float4 x1 = __ldg(qa + p + 1), y1 = __ldg(ja + p + 1);
        a0 = fmaf(x0.x, y0.x, a0); a0 = fmaf(x0.y, y0.y, a0);
        a0 = fmaf(x0.z, y0.z, a0); a0 = fmaf(x0.w, y0.w, a0);
        a1 = fmaf(x1.x, y1.x, a1); a1 = fmaf(x1.y, y1.y, a1);
        a1 = fmaf(x1.z, y1.z, a1); a1 = fmaf(x1.w, y1.w, a1);
    }
    float acc = a0 + a1;
    if (acc > be || (acc == be && j < bi)) { be = acc; bi = j; }
}

__device__ __forceinline__ void mma16816(float c[4], const unsigned a[4],
                                         unsigned b0, unsigned b1) {
    asm volatile(
        "mma.sync.aligned.m16n8k16.row.col.f32.bf16.bf16.f32 "
        "{%0,%1,%2,%3}, {%4,%5,%6,%7}, {%8,%9}, {%0,%1,%2,%3};"
        : "+f"(c[0]), "+f"(c[1]), "+f"(c[2]), "+f"(c[3])
        : "r"(a[0]), "r"(a[1]), "r"(a[2]), "r"(a[3]), "r"(b0), "r"(b1));
}

__global__ __launch_bounds__(THREADS, 2)
void sim_kernel(const float* __restrict__ emb,
                const int* __restrict__ item_idx) {
    __shared__ __align__(16) __nv_bfloat16 qs[QB * DIM];             // 16 KB
    __shared__ __align__(16) __nv_bfloat16 its[2 * ITEM_TILE * DIM]; // 16 KB x2buf
    __shared__ int selfs[QB];

    const int tid   = threadIdx.x;
    const int warp  = tid >> 5;
    const int lane  = tid & 31;
    const int qbase = blockIdx.y * QB;
    const int wq    = warp * 16;

    // ---- self indices (item_idx is int32 under JAX default promotion)
    for (int q = tid; q < QB; q += THREADS) {
        int s = item_idx[qbase + q] - 1;
        if (s < 0) s += N_ITEMS;               // python negative-index wrap
        selfs[q] = max(0, min(s, N_ITEMS - 1));
    }
    __syncthreads();

    // ---- stage query rows as bf16 (linear 128B rows)
    for (int i = tid; i < QB * (DIM / 4); i += THREADS) {
        int q = i >> 4, p = i & 15;
        float4 v = __ldg((const float4*)(emb + (size_t)selfs[q] * DIM) + p);
        *(uint2*)((char*)qs + q * 128 + p * 8) =
            make_uint2(pack_bf16x2(v.x, v.y), pack_bf16x2(v.z, v.w));
    }
    __syncthreads();

    // ---- A fragments: warp's 16 query rows, K=64, resident in 16 regs
    unsigned a[4][4];
    {
        unsigned qaddr = (unsigned)__cvta_generic_to_shared(qs)
                       + (unsigned)((wq + (lane & 15)) * 128 + (lane >> 4) * 16);
        #pragma unroll
        for (int kt = 0; kt < 4; kt++) {
            asm volatile("ldmatrix.sync.aligned.m8n8.x4.shared.b16 {%0,%1,%2,%3}, [%4];"
                         : "=r"(a[kt][0]), "=r"(a[kt][1]), "=r"(a[kt][2]), "=r"(a[kt][3])
                         : "r"(qaddr + kt * 32));
        }
    }

    const int t4 = lane & 3;            // column pair within mma
    const int g  = lane >> 2;           // row within 16-row block
    const int self0 = selfs[wq + g];
    const int self1 = selfs[wq + g + 8];
    const int myrow_self = selfs[wq + (lane & 15)];

    // seed thresholds from g_best (monotone lower bound; stale reads safe)
    float run0, run1;
    {
        unsigned long long p0 = __ldcg(&g_best[qbase + wq + g]);
        unsigned long long p1 = __ldcg(&g_best[qbase + wq + g + 8]);
        run0 = ord2f((unsigned)(p0 >> 32));
        run1 = ord2f((unsigned)(p1 >> 32));
    }
    float thr0 = run0 - MARGIN, thr1 = run1 - MARGIN;

    float be0 = NINF, be1 = NINF;       // exact best among rescored
    int   bi0 = 0x7FFFFFFF, bi1 = 0x7FFFFFFF;

    const unsigned its_base = (unsigned)__cvta_generic_to_shared(its);
    // ldmatrix.x4 B addressing: r=row-in-group, mk=k-half, mg=item-subgroup
    const int r  = lane & 7;
    const int mk = (lane >> 3) & 1;
    const int mg = (lane >> 4) & 1;

    const int tile0 = blockIdx.x * TILES_PER_CHUNK;   // global 64-item tile id

    // cp.async tile prefetch: 8 KB contiguous bf16, swizzled into smem
    auto issue_tile = [&](int gt, int buf) {
        #pragma unroll
        for (int s = 0; s < 2; s++) {
            int seg = tid + s * THREADS;              // 0..511 (16B segments)
            int it = seg >> 3, p16 = seg & 7;
            const char* src = (const char*)g_emb16 + (size_t)gt * 8192 + seg * 16;
            unsigned dst = its_base + buf * 8192 + it * 128
                         + ((p16 * 16) ^ ((it & 7) * 16));
            asm volatile("cp.async.cg.shared.global [%0], [%1], 16;"
                         :: "r"(dst), "l"(src));
        }
    };

    issue_tile(tile0, 0);
    asm volatile("cp.async.commit_group;");
    issue_tile(tile0 + 1, 1);
    asm volatile("cp.async.commit_group;");

    for (int t = 0; t < TILES_PER_CHUNK; t++) {
        asm volatile("cp.async.wait_group 1;");
        __syncthreads();

        const int tb = (tile0 + t) * ITEM_TILE;       // global item base
        const unsigned bufb = its_base + (t & 1) * 8192;
        const bool need_mask =
            (__ballot_sync(FULL, (unsigned)(myrow_self - tb) < (unsigned)ITEM_TILE) != 0u)
            || (tb + ITEM_TILE > N_ITEMS);

        #pragma unroll
        for (int ng = 0; ng < 8; ng += 2) {
            float c0[4] = {0.f, 0.f, 0.f, 0.f};
            float c1[4] = {0.f, 0.f, 0.f, 0.f};
            #pragma unroll
            for (int kt = 0; kt < 4; kt++) {
                unsigned addr = bufb + (unsigned)((ng * 8 + mg * 8 + r) * 128)
                              + (unsigned)((kt * 32 + mk * 16) ^ (r * 16));
                unsigned b0, b1, b2, b3;
                asm volatile("ldmatrix.sync.aligned.m8n8.x4.shared.b16 {%0,%1,%2,%3}, [%4];"
                             : "=r"(b0), "=r"(b1), "=r"(b2), "=r"(b3) : "r"(addr));
                mma16816(c0, a[kt], b0, b1);
                mma16816(c1, a[kt], b2, b3);
            }
            #pragma unroll
            for (int half = 0; half < 2; half++) {
                float* c = half ? c1 : c0;
                int jb = tb + (ng + half) * 8;
                int col0 = jb + 2 * t4, col1 = col0 + 1;
                if (need_mask) {
                    if (col0 == self0 || col0 >= N_ITEMS) c[0] = NINF;
                    if (col1 == self0 || col1 >= N_ITEMS) c[1] = NINF;
                    if (col0 == self1 || col0 >= N_ITEMS) c[2] = NINF;
                    if (col1 == self1 || col1 >= N_ITEMS) c[3] = NINF;
                }
                run0 = fmaxf(run0, fmaxf(c[0], c[1]));   // lane-local
                run1 = fmaxf(run1, fmaxf(c[2], c[3]));
                if ((c[0] >= thr0) | (c[1] >= thr0) | (c[2] >= thr1) | (c[3] >= thr1)) {
                    if (c[0] >= thr0 && col0 != self0 && col0 < N_ITEMS)
                        rescore(emb, self0, col0, be0, bi0);
                    if (c[1] >= thr0 && col1 != self0 && col1 < N_ITEMS)
                        rescore(emb, self0, col1, be0, bi0);
                    if (c[2] >= thr1 && col0 != self1 && col0 < N_ITEMS)
                        rescore(emb, self1, col0, be1, bi1);
                    if (c[3] >= thr1 && col1 != self1 && col1 < N_ITEMS)
                        rescore(emb, self1, col1, be1, bi1);
                }
            }
        }

        __syncthreads();   // all warps done with buf[t&1] before refill
        if (t + 2 < TILES_PER_CHUNK) issue_tile(tile0 + t + 2, t & 1);
        asm volatile("cp.async.commit_group;");  // empty group ok, keeps count

        // tighten thresholds once per tile (cross-lane reduce of run-max)
        run0 = fmaxf(run0, __shfl_xor_sync(FULL, run0, 1));
        run0 = fmaxf(run0, __shfl_xor_sync(FULL, run0, 2));
        run1 = fmaxf(run1, __shfl_xor_sync(FULL, run1, 1));
        run1 = fmaxf(run1, __shfl_xor_sync(FULL, run1, 2));
        thr0 = run0 - MARGIN;
        thr1 = run1 - MARGIN;
    }

    // combine the 4 lanes of each row (tie -> smaller index)
    #pragma unroll
    for (int m = 1; m <= 2; m <<= 1) {
        float so = __shfl_xor_sync(FULL, be0, m);
        int   io = __shfl_xor_sync(FULL, bi0, m);
        if (so > be0 || (so == be0 && io < bi0)) { be0 = so; bi0 = io; }
        so = __shfl_xor_sync(FULL, be1, m);
        io = __shfl_xor_sync(FULL, bi1, m);
        if (so > be1 || (so == be1 && io < bi1)) { be1 = so; bi1 = io; }
    }
    if (t4 == 0) {
        if (be0 > NINF) {
            unsigned long long pk =
                ((unsigned long long)f2ord(be0) << 32) | (unsigned)(~bi0);
            atomicMax(&g_best[qbase + wq + g], pk);
        }
        if (be1 > NINF) {
            unsigned long long pk =
                ((unsigned long long)f2ord(be1) << 32) | (unsigned)(~bi1);
            atomicMax(&g_best[qbase + wq + g + 8], pk);
        }
    }
}

__global__ void finalize_kernel(const float* __restrict__ minv,
                                const float* __restrict__ maxv,
                                float* __restrict__ out) {
    int i = blockIdx.x * blockDim.x + threadIdx.x;
    if (i < BATCH) {
        unsigned long long p = g_best[i];
        float raw = ord2f((unsigned int)(p >> 32));
        int   idx = (int)(~(unsigned int)(p & 0xFFFFFFFFull));
        float mn = minv[0], mx = maxv[0];
        float score = (raw - mn) / (mx - mn);
        out[i]         = (float)(idx + 1);   // indices (argmax + 1), exact < 2^24
        out[BATCH + i] = score;              // normalized scores (fp32 output)
    }
}

extern "C" void kernel_launch(void* const* d_in, const int* in_sizes, int n_in,
                              void* d_out, int out_size) {
    const float* emb = (const float*)d_in[0];
    const int*   idx = (const int*)d_in[1];
    const float* mn  = (const float*)d_in[2];
    const float* mx  = (const float*)d_in[3];

    reset_kernel<<<(BATCH + 255) / 256, 256>>>();
    convert_kernel<<<2048, 256>>>(emb);

    dim3 grid(NCHUNKS, BATCH / QB);
    sim_kernel<<<grid, THREADS>>>(emb, idx);

    finalize_kernel<<<(BATCH + 255) / 256, 256>>>(mn, mx, (float*)d_out);
}

// round 13
// speedup vs baseline: 4.8289x; 3.6039x over previous
#include <cuda_runtime.h>
#include <cuda_bf16.h>
#include <cstdint>

#define N_ITEMS 500000
#define DIM 64
#define BATCH 1024
#define QB 128              // queries per CTA (8 warps x 16 rows)
#define THREADS 256
#define ITEM_TILE 64
#define CHUNK 4096          // items per CTA chunk -> 64 tiles
#define NCHUNKS 123
#define N_PAD (NCHUNKS * CHUNK)              // 503808, zero-padded bf16 copy
#define TILES_PER_CHUNK (CHUNK / ITEM_TILE)  // 64
#define MARGIN 1.0f         // >= 2*eps(bf16 dot) ~ 0.4 worst-case; 2.5x safety
#define NINF __uint_as_float(0xFF800000u)
#define FULL 0xFFFFFFFFu

// Scratch (static __device__ arrays -- the sanctioned mechanism)
__device__ unsigned long long g_best[BATCH];             // exact packed best
__device__ unsigned g_amax[BATCH];                       // approx max (ordered f32)
__device__ __nv_bfloat16 g_emb16[(size_t)N_PAD * DIM];   // 64.5 MB bf16 copy

__device__ __forceinline__ unsigned f2ord(float f) {
    unsigned b = __float_as_uint(f);
    return (b & 0x80000000u) ? ~b : (b | 0x80000000u);
}
__device__ __forceinline__ float ord2f(unsigned o) {
    unsigned b = (o & 0x80000000u) ? (o & 0x7FFFFFFFu) : ~o;
    return __uint_as_float(b);
}
__device__ __forceinline__ unsigned pack_bf16x2(float x, float y) {
    __nv_bfloat162 p = __floats2bfloat162_rn(x, y);
    return *(unsigned*)&p;
}

__global__ void reset_kernel() {
    int i = blockIdx.x * blockDim.x + threadIdx.x;
    if (i < BATCH) {
        g_best[i] = ((unsigned long long)f2ord(NINF) << 32) | 0xFFFFFFFFull;
        g_amax[i] = f2ord(NINF);
    }
}

// fp32 -> bf16 preconversion (zero-pad beyond N_ITEMS)
__global__ void convert_kernel(const float* __restrict__ emb) {
    const int total = N_PAD * (DIM / 4);
    const int real  = N_ITEMS * (DIM / 4);
    for (int i = blockIdx.x * blockDim.x + threadIdx.x; i < total;
         i += gridDim.x * blockDim.x) {
        float4 v = (i < real) ? __ldg((const float4*)emb + i)
                              : make_float4(0.f, 0.f, 0.f, 0.f);
        ((uint2*)g_emb16)[i] = make_uint2(pack_bf16x2(v.x, v.y),
                                          pack_bf16x2(v.z, v.w));
    }
}

// Exact fp32 rescore; accumulation order IDENTICAL to R6 -> deterministic
// cross-chunk argmax via packed atomicMax (tie -> smaller index).
__device__ __forceinline__ void rescore(const float* __restrict__ emb,
                                        int qrow, int j, float& be, int& bi) {
    const float4* qa = (const float4*)(emb + (size_t)qrow * DIM);
    const float4* ja = (const float4*)(emb + (size_t)j * DIM);
    float a0 = 0.f, a1 = 0.f;
    #pragma unroll
    for (int p = 0; p < 16; p += 2) {
        float4 x0 = __ldg(qa + p),     y0 = __ldg(ja + p);
        float4 x1 = __ldg(qa + p + 1), y1 = __ldg(ja + p + 1);
        a0 = fmaf(x0.x, y0.x, a0); a0 = fmaf(x0.y, y0.y, a0);
        a0 = fmaf(x0.z, y0.z, a0); a0 = fmaf(x0.w, y0.w, a0);
        a1 = fmaf(x1.x, y1.x, a1); a1 = fmaf(x1.y, y1.y, a1);
        a1 = fmaf(x1.z, y1.z, a1); a1 = fmaf(x1.w, y1.w, a1);
    }
    float acc = a0 + a1;
    if (acc > be || (acc == be && j < bi)) { be = acc; bi = j; }
}

__device__ __forceinline__ void mma16816(float c[4], const unsigned a[4],
                                         unsigned b0, unsigned b1) {
    asm volatile(
        "mma.sync.aligned.m16n8k16.row.col.f32.bf16.bf16.f32 "
        "{%0,%1,%2,%3}, {%4,%5,%6,%7}, {%8,%9}, {%0,%1,%2,%3};"
        : "+f"(c[0]), "+f"(c[1]), "+f"(c[2]), "+f"(c[3])
        : "r"(a[0]), "r"(a[1]), "r"(a[2]), "r"(a[3]), "r"(b0), "r"(b1));
}

// PASS 1: pure bf16 max-scan (no rescoring). PASS 2: fixed-threshold candidate
// detection + exact fp32 rescore (expected ~3 hits per query in total).
template <int PASS>
__global__ __launch_bounds__(THREADS, 2)
void sim_pass(const float* __restrict__ emb,
              const int* __restrict__ item_idx) {
    __shared__ __align__(16) __nv_bfloat16 qs[QB * DIM];             // 16 KB
    __shared__ __align__(16) __nv_bfloat16 its[2 * ITEM_TILE * DIM]; // 32 KB 2buf
    __shared__ int selfs[QB];

    const int tid   = threadIdx.x;
    const int warp  = tid >> 5;
    const int lane  = tid & 31;
    const int qbase = blockIdx.y * QB;
    const int wq    = warp * 16;

    // ---- self indices (item_idx is int32 under JAX default promotion)
    for (int q = tid; q < QB; q += THREADS) {
        int s = item_idx[qbase + q] - 1;
        if (s < 0) s += N_ITEMS;               // python negative-index wrap
        selfs[q] = max(0, min(s, N_ITEMS - 1));
    }
    __syncthreads();

    // ---- stage query rows as bf16 (linear 128B rows)
    for (int i = tid; i < QB * (DIM / 4); i += THREADS) {
        int q = i >> 4, p = i & 15;
        float4 v = __ldg((const float4*)(emb + (size_t)selfs[q] * DIM) + p);
        *(uint2*)((char*)qs + q * 128 + p * 8) =
            make_uint2(pack_bf16x2(v.x, v.y), pack_bf16x2(v.z, v.w));
    }
    __syncthreads();

    // ---- A fragments: warp's 16 query rows, K=64, resident in 16 regs
    unsigned a[4][4];
    {
        unsigned qaddr = (unsigned)__cvta_generic_to_shared(qs)
                       + (unsigned)((wq + (lane & 15)) * 128 + (lane >> 4) * 16);
        #pragma unroll
        for (int kt = 0; kt < 4; kt++) {
            asm volatile("ldmatrix.sync.aligned.m8n8.x4.shared.b16 {%0,%1,%2,%3}, [%4];"
                         : "=r"(a[kt][0]), "=r"(a[kt][1]), "=r"(a[kt][2]), "=r"(a[kt][3])
                         : "r"(qaddr + kt * 32));
        }
    }

    const int t4 = lane & 3;            // column pair within mma
    const int g  = lane >> 2;           // row within 16-row block
    const int self0 = selfs[wq + g];
    const int self1 = selfs[wq + g + 8];
    const int myrow_self = selfs[wq + (lane & 15)];

    float run0 = NINF, run1 = NINF;     // pass1: running approx max
    float thr0 = NINF, thr1 = NINF;     // pass2: fixed thresholds
    if (PASS == 2) {
        thr0 = ord2f(g_amax[qbase + wq + g]) - MARGIN;
        thr1 = ord2f(g_amax[qbase + wq + g + 8]) - MARGIN;
    }
    float be0 = NINF, be1 = NINF;       // pass2: exact best among rescored
    int   bi0 = 0x7FFFFFFF, bi1 = 0x7FFFFFFF;

    const unsigned its_base = (unsigned)__cvta_generic_to_shared(its);
    const int r  = lane & 7;            // ldmatrix.x4 B addressing
    const int mk = (lane >> 3) & 1;
    const int mg = (lane >> 4) & 1;

    const int tile0 = blockIdx.x * TILES_PER_CHUNK;

    auto issue_tile = [&](int gt, int buf) {
        #pragma unroll
        for (int s = 0; s < 2; s++) {
            int seg = tid + s * THREADS;              // 16B segments
            int it = seg >> 3, p16 = seg & 7;
            const char* src = (const char*)g_emb16 + (size_t)gt * 8192 + seg * 16;
            unsigned dst = its_base + buf * 8192 + it * 128
                         + ((p16 * 16) ^ ((it & 7) * 16));
            asm volatile("cp.async.cg.shared.global [%0], [%1], 16;"
                         :: "r"(dst), "l"(src));
        }
    };

    issue_tile(tile0, 0);
    asm volatile("cp.async.commit_group;");
    issue_tile(tile0 + 1, 1);
    asm volatile("cp.async.commit_group;");

    for (int t = 0; t < TILES_PER_CHUNK; t++) {
        asm volatile("cp.async.wait_group 1;");
        __syncthreads();

        const int tb = (tile0 + t) * ITEM_TILE;
        const unsigned bufb = its_base + (t & 1) * 8192;
        const bool need_mask =
            (__ballot_sync(FULL, (unsigned)(myrow_self - tb) < (unsigned)ITEM_TILE) != 0u)
            || (tb + ITEM_TILE > N_ITEMS);

        #pragma unroll
        for (int ng = 0; ng < 8; ng += 2) {
            float c0[4] = {0.f, 0.f, 0.f, 0.f};
            float c1[4] = {0.f, 0.f, 0.f, 0.f};
            #pragma unroll
            for (int kt = 0; kt < 4; kt++) {
                unsigned addr = bufb + (unsigned)((ng * 8 + mg * 8 + r) * 128)
                              + (unsigned)((kt * 32 + mk * 16) ^ (r * 16));
                unsigned b0, b1, b2, b3;
                asm volatile("ldmatrix.sync.aligned.m8n8.x4.shared.b16 {%0,%1,%2,%3}, [%4];"
                             : "=r"(b0), "=r"(b1), "=r"(b2), "=r"(b3) : "r"(addr));
                mma16816(c0, a[kt], b0, b1);
                mma16816(c1, a[kt], b2, b3);
            }
            #pragma unroll
            for (int half = 0; half < 2; half++) {
                float* c = half ? c1 : c0;
                int jb = tb + (ng + half) * 8;
                int col0 = jb + 2 * t4, col1 = col0 + 1;
                if (PASS == 1) {
                    if (need_mask) {   // exclude self and padded cols from max
                        if (col0 == self0 || col0 >= N_ITEMS) c[0] = NINF;
                        if (col1 == self0 || col1 >= N_ITEMS) c[1] = NINF;
                        if (col0 == self1 || col0 >= N_ITEMS) c[2] = NINF;
                        if (col1 == self1 || col1 >= N_ITEMS) c[3] = NINF;
                    }
                    run0 = fmaxf(run0, fmaxf(c[0], c[1]));
                    run1 = fmaxf(run1, fmaxf(c[2], c[3]));
                } else {
                    // fixed thresholds; hits are ~3 per query over the WHOLE grid
                    if (fmaxf(c[0], c[1]) >= thr0 || fmaxf(c[2], c[3]) >= thr1) {
                        if (c[0] >= thr0 && col0 != self0 && col0 < N_ITEMS)
                            rescore(emb, self0, col0, be0, bi0);
                        if (c[1] >= thr0 && col1 != self0 && col1 < N_ITEMS)
                            rescore(emb, self0, col1, be0, bi0);
                        if (c[2] >= thr1 && col0 != self1 && col0 < N_ITEMS)
                            rescore(emb, self1, col0, be1, bi1);
                        if (c[3] >= thr1 && col1 != self1 && col1 < N_ITEMS)
                            rescore(emb, self1, col1, be1, bi1);
                    }
                }
            }
        }

        __syncthreads();   // all warps done with buf[t&1] before refill
        if (t + 2 < TILES_PER_CHUNK) issue_tile(tile0 + t + 2, t & 1);
        asm volatile("cp.async.commit_group;");  // empty group ok, keeps count
    }

    if (PASS == 1) {
        // reduce run-max across the 4 lanes of each row, publish approx max
        run0 = fmaxf(run0, __shfl_xor_sync(FULL, run0, 1));
        run0 = fmaxf(run0, __shfl_xor_sync(FULL, run0, 2));
        run1 = fmaxf(run1, __shfl_xor_sync(FULL, run1, 1));
        run1 = fmaxf(run1, __shfl_xor_sync(FULL, run1, 2));
        if (t4 == 0) {
            atomicMax(&g_amax[qbase + wq + g],     f2ord(run0));
            atomicMax(&g_amax[qbase + wq + g + 8], f2ord(run1));
        }
    } else {
        // combine the 4 lanes of each row (tie -> smaller index)
        #pragma unroll
        for (int m = 1; m <= 2; m <<= 1) {
            float so = __shfl_xor_sync(FULL, be0, m);
            int   io = __shfl_xor_sync(FULL, bi0, m);
            if (so > be0 || (so == be0 && io < bi0)) { be0 = so; bi0 = io; }
            so = __shfl_xor_sync(FULL, be1, m);
            io = __shfl_xor_sync(FULL, bi1, m);
            if (so > be1 || (so == be1 && io < bi1)) { be1 = so; bi1 = io; }
        }
        if (t4 == 0) {
            if (be0 > NINF) {
                unsigned long long pk =
                    ((unsigned long long)f2ord(be0) << 32) | (unsigned)(~bi0);
                atomicMax(&g_best[qbase + wq + g], pk);
            }
            if (be1 > NINF) {
                unsigned long long pk =
                    ((unsigned long long)f2ord(be1) << 32) | (unsigned)(~bi1);
                atomicMax(&g_best[qbase + wq + g + 8], pk);
            }
        }
    }
}

__global__ void finalize_kernel(const float* __restrict__ minv,
                                const float* __restrict__ maxv,
                                float* __restrict__ out) {
    int i = blockIdx.x * blockDim.x + threadIdx.x;
    if (i < BATCH) {
        unsigned long long p = g_best[i];
        float raw = ord2f((unsigned)(p >> 32));
        int   idx = (int)(~(unsigned)(p & 0xFFFFFFFFull));
        float mn = minv[0], mx = maxv[0];
        float score = (raw - mn) / (mx - mn);
        out[i]         = (float)(idx + 1);   // indices (argmax + 1), exact < 2^24
        out[BATCH + i] = score;              // normalized scores (fp32 output)
    }
}

extern "C" void kernel_launch(void* const* d_in, const int* in_sizes, int n_in,
                              void* d_out, int out_size) {
    const float* emb = (const float*)d_in[0];
    const int*   idx = (const int*)d_in[1];
    const float* mn  = (const float*)d_in[2];
    const float* mx  = (const float*)d_in[3];

    reset_kernel<<<(BATCH + 255) / 256, 256>>>();
    convert_kernel<<<2048, 256>>>(emb);

    dim3 grid(NCHUNKS, BATCH / QB);
    sim_pass<1><<<grid, THREADS>>>(emb, idx);   // approx max per query
    sim_pass<2><<<grid, THREADS>>>(emb, idx);   // band detect + exact rescore

    finalize_kernel<<<(BATCH + 255) / 256, 256>>>(mn, mx, (float*)d_out);
}